// round 4
// baseline (speedup 1.0000x reference)
#include <cuda_runtime.h>
#include <cuda_bf16.h>
#include <cstdint>
#include <cstddef>

#define BS 64
#define MU 64
#define KA 64
#define DD 128
#define HH 128

#define ROWP 136                 // padded bf16 elems per smem row (272 B)
#define TILE_R 128               // rows per k3 tile
#define N_TILES 2048             // 262144 / 128
#define K3_THREADS 256

// Scratch (device globals: allocation-free per harness rules)
__device__ float g_msgm_part[4][BS * MU * DD];   // 8 MB
__device__ float g_msgk_part[8][BS * KA * DD];   // 16 MB
__device__ float g_zm[BS * MU * HH];             // 2 MB
__device__ float g_zk[BS * KA * HH];             // 2 MB

__device__ __forceinline__ uint32_t smem_u32(const void* p) {
    uint32_t a;
    asm("{ .reg .u64 t; cvta.to.shared.u64 t, %1; cvt.u32.u64 %0, t; }" : "=r"(a) : "l"(p));
    return a;
}

#define LDSM_X4(r0, r1, r2, r3, addr) \
    asm volatile("ldmatrix.sync.aligned.m8n8.x4.shared.b16 {%0,%1,%2,%3}, [%4];" \
                 : "=r"(r0), "=r"(r1), "=r"(r2), "=r"(r3) : "r"(addr))

// ===========================================================================
// K1: grid = 64b x 8mc x 4kc = 2048 blocks, 128 threads (t = d index).
// All-register accumulation: 16 k-accs + 1 m-acc. No smem, no atomics.
// ===========================================================================
__global__ void __launch_bounds__(128) k1_reduce(const float* __restrict__ in) {
    int bid = blockIdx.x;
    int b = bid >> 5;
    int mc = (bid >> 2) & 7;
    int kc = bid & 3;
    int t = threadIdx.x;

    const float* base = in + ((size_t)((b * MU + mc * 8) * KA + kc * 16)) * DD + t;
    float ak[16];
#pragma unroll
    for (int k = 0; k < 16; k++) ak[k] = 0.f;

#pragma unroll 1
    for (int m = 0; m < 8; m++) {
        const float* pm = base + (size_t)m * KA * DD;
        float v[16];
#pragma unroll
        for (int k = 0; k < 16; k++) v[k] = pm[(size_t)k * DD];
        float am = 0.f;
#pragma unroll
        for (int k = 0; k < 16; k++) { am += v[k]; ak[k] += v[k]; }
        g_msgm_part[kc][(size_t)(b * MU + mc * 8 + m) * DD + t] = am;
    }
#pragma unroll
    for (int k = 0; k < 16; k++)
        g_msgk_part[mc][(size_t)(b * KA + kc * 16 + k) * DD + t] = ak[k];
}

// ===========================================================================
// K2: zm = msg_m @ Wm^T ; zk = msg_k @ Wk^T  (exact fp32, 8x8 reg tiles)
// ===========================================================================
__global__ void __launch_bounds__(128) k2_bias(const float* __restrict__ Wm,
                                               const float* __restrict__ Wk) {
    extern __shared__ float s2[];
    float* Ws = s2;               // [128][129]
    float* Ms = s2 + 128 * 129;   // [64][129]
    int side = blockIdx.x >> 6;
    int b = blockIdx.x & 63;
    int t = threadIdx.x;

    const float* W = side ? Wk : Wm;
#pragma unroll 4
    for (int i = 0; i < HH; i++) Ws[i * 129 + t] = W[i * DD + t];

    if (!side) {
#pragma unroll 2
        for (int r = 0; r < 64; r++) {
            float s = 0.f;
#pragma unroll
            for (int p = 0; p < 4; p++) s += g_msgm_part[p][(size_t)(b * 64 + r) * DD + t];
            Ms[r * 129 + t] = s;
        }
    } else {
#pragma unroll 2
        for (int r = 0; r < 64; r++) {
            float s = 0.f;
#pragma unroll
            for (int p = 0; p < 8; p++) s += g_msgk_part[p][(size_t)(b * 64 + r) * DD + t];
            Ms[r * 129 + t] = s;
        }
    }
    __syncthreads();

    int rt = t >> 4;
    int ht = t & 15;
    float acc[8][8];
#pragma unroll
    for (int i = 0; i < 8; i++)
#pragma unroll
        for (int j = 0; j < 8; j++) acc[i][j] = 0.f;

    for (int dd = 0; dd < DD; dd++) {
        float xv[8], wv[8];
#pragma unroll
        for (int i = 0; i < 8; i++) xv[i] = Ms[(rt * 8 + i) * 129 + dd];
#pragma unroll
        for (int j = 0; j < 8; j++) wv[j] = Ws[(ht + 16 * j) * 129 + dd];
#pragma unroll
        for (int i = 0; i < 8; i++)
#pragma unroll
            for (int j = 0; j < 8; j++) acc[i][j] += xv[i] * wv[j];
    }

    float* outp = side ? g_zk : g_zm;
#pragma unroll
    for (int i = 0; i < 8; i++)
#pragma unroll
        for (int j = 0; j < 8; j++)
            outp[(size_t)(b * 64 + rt * 8 + i) * HH + ht + 16 * j] = acc[i][j];
}

// ===========================================================================
// K3: persistent bf16 mma.sync m16n8k16 GEMM + fused bias epilogue.
// Grid 296 (2 CTA/SM for load/compute overlap), 256 threads (8 warps).
// Warp w owns rows [w*16, w*16+16) x all 128 cols of a 128-row tile.
// Fragments via ldmatrix.x4 (72 LDSM vs 288 LDS per warp-tile).
// SMEM/CTA: B [128][136] 34816 B + A0/A1 [128][136] 2x34816 = 104448 B.
// ===========================================================================
#define K3_SMEM (3 * 34816)

__device__ __forceinline__ void load_tile_bf16(const float* __restrict__ src,
                                               __nv_bfloat16* __restrict__ dst,
                                               int t, int rows) {
    const float4* s4 = reinterpret_cast<const float4*>(src);
    int n4 = rows * 32;
    for (int i = t; i < n4; i += K3_THREADS) {
        int r = i >> 5, c4 = i & 31;
        float4 v = s4[i];
        __nv_bfloat162 p0 = __floats2bfloat162_rn(v.x, v.y);
        __nv_bfloat162 p1 = __floats2bfloat162_rn(v.z, v.w);
        uint2 u;
        u.x = *reinterpret_cast<uint32_t*>(&p0);
        u.y = *reinterpret_cast<uint32_t*>(&p1);
        *reinterpret_cast<uint2*>(dst + r * ROWP + c4 * 4) = u;
    }
}

__global__ void __launch_bounds__(K3_THREADS, 2) k3_main(const float* __restrict__ in,
                                                         const float* __restrict__ Wself,
                                                         float* __restrict__ out) {
    extern __shared__ __nv_bfloat16 smem[];
    __nv_bfloat16* Bs = smem;                       // [128][136]
    __nv_bfloat16* A0 = smem + 128 * ROWP;          // [128][136]
    __nv_bfloat16* A1 = A0 + 128 * ROWP;

    int t = threadIdx.x;
    int wid = t >> 5, lane = t & 31;
    int lr = lane >> 2, lc = lane & 3;
    int r0 = wid * 16;                              // warp row strip in tile

    load_tile_bf16(Wself, Bs, t, 128);
    load_tile_bf16(in + (size_t)blockIdx.x * TILE_R * DD, A0, t, TILE_R);
    __syncthreads();

    // ldmatrix per-lane byte offsets (within a tile buffer / Bs)
    // A x4: mats (rows0-7,k0),(rows8-15,k0),(rows0-7,k+8),(rows8-15,k+8)
    uint32_t a_off = (uint32_t)((r0 + (lane & 7) + ((lane & 8) ? 8 : 0)) * 272 +
                                ((lane & 16) ? 16 : 0));
    // B x4: mats (n0-7,k0),(n0-7,k+8),(n8-15,k0),(n8-15,k+8)
    uint32_t b_addr0 = smem_u32(Bs) +
                       (uint32_t)((((lane & 16) ? 8 : 0) + (lane & 7)) * 272 +
                                  ((lane & 8) ? 16 : 0));
    uint32_t a_addr0 = smem_u32(A0) + a_off;
    uint32_t a_addr1 = smem_u32(A1) + a_off;

    int it = 0;
    for (int tile = blockIdx.x; tile < N_TILES; tile += gridDim.x, it++) {
        uint32_t a_cur = (it & 1) ? a_addr1 : a_addr0;
        __nv_bfloat16* nxt = (it & 1) ? A0 : A1;

        // Prefetch next tile (LDGs in flight; co-resident CTA hides STS stalls)
        int ntile = tile + gridDim.x;
        if (ntile < N_TILES)
            load_tile_bf16(in + (size_t)ntile * TILE_R * DD, nxt, t, TILE_R);

        // ---- MMA: rows [r0, r0+16) x 128 cols, K = 128 ----
        float acc[16][4];
#pragma unroll
        for (int nt = 0; nt < 16; nt++)
#pragma unroll
            for (int q = 0; q < 4; q++) acc[nt][q] = 0.f;

#pragma unroll
        for (int kk = 0; kk < 8; kk++) {
            uint32_t a0, a1, a2, a3;
            LDSM_X4(a0, a1, a2, a3, a_cur + kk * 32);
#pragma unroll
            for (int np = 0; np < 8; np++) {
                uint32_t b0, b1, b2, b3;
                LDSM_X4(b0, b1, b2, b3, b_addr0 + np * 16 * 272 + kk * 32);
                asm volatile(
                    "mma.sync.aligned.m16n8k16.row.col.f32.bf16.bf16.f32 "
                    "{%0,%1,%2,%3},{%4,%5,%6,%7},{%8,%9},{%0,%1,%2,%3};"
                    : "+f"(acc[2 * np][0]), "+f"(acc[2 * np][1]),
                      "+f"(acc[2 * np][2]), "+f"(acc[2 * np][3])
                    : "r"(a0), "r"(a1), "r"(a2), "r"(a3), "r"(b0), "r"(b1));
                asm volatile(
                    "mma.sync.aligned.m16n8k16.row.col.f32.bf16.bf16.f32 "
                    "{%0,%1,%2,%3},{%4,%5,%6,%7},{%8,%9},{%0,%1,%2,%3};"
                    : "+f"(acc[2 * np + 1][0]), "+f"(acc[2 * np + 1][1]),
                      "+f"(acc[2 * np + 1][2]), "+f"(acc[2 * np + 1][3])
                    : "r"(a0), "r"(a1), "r"(a2), "r"(a3), "r"(b2), "r"(b3));
            }
        }

        // ---- Epilogue: + zm[bm,:] + zk[bk,:], direct STG.64 (32B sectors) ----
        int grow = tile * TILE_R + r0 + lr;          // global row (lr part)
        int bm = grow >> 6;                          // b*64 + m (same for +8 row)
        int bk = ((grow >> 12) << 6) | (grow & 63);  // b*64 + k
        const float2* zmrow = reinterpret_cast<const float2*>(g_zm + (size_t)bm * HH);
        const float2* zkr0 = reinterpret_cast<const float2*>(g_zk + (size_t)bk * HH);
        const float2* zkr8 = reinterpret_cast<const float2*>(g_zk + (size_t)(bk + 8) * HH);
        float2* o0 = reinterpret_cast<float2*>(out + (size_t)grow * HH);
        float2* o8 = reinterpret_cast<float2*>(out + (size_t)(grow + 8) * HH);

#pragma unroll
        for (int nt = 0; nt < 16; nt++) {
            int cw = nt * 4 + lc;                    // float2 column index
            float2 zm2 = zmrow[cw];
            float2 za = zkr0[cw];
            float2 zb = zkr8[cw];
            float2 v0, v8;
            v0.x = acc[nt][0] + zm2.x + za.x;
            v0.y = acc[nt][1] + zm2.y + za.y;
            v8.x = acc[nt][2] + zm2.x + zb.x;
            v8.y = acc[nt][3] + zm2.y + zb.y;
            o0[cw] = v0;
            o8[cw] = v8;
        }
        __syncthreads();
    }
}

// ===========================================================================
extern "C" void kernel_launch(void* const* d_in, const int* in_sizes, int n_in,
                              void* d_out, int out_size) {
    const float* inputs = (const float*)d_in[0];
    const float* Wself  = (const float*)d_in[1];
    const float* Wm     = (const float*)d_in[2];
    const float* Wk     = (const float*)d_in[3];
    float* out = (float*)d_out;
    (void)in_sizes; (void)n_in; (void)out_size;

    const size_t S2 = (size_t)(128 * 129 + 64 * 129) * sizeof(float);
    cudaFuncSetAttribute(k2_bias, cudaFuncAttributeMaxDynamicSharedMemorySize, (int)S2);
    cudaFuncSetAttribute(k3_main, cudaFuncAttributeMaxDynamicSharedMemorySize, K3_SMEM);

    k1_reduce<<<2048, 128>>>(inputs);
    k2_bias<<<128, 128, S2>>>(Wm, Wk);
    k3_main<<<296, K3_THREADS, K3_SMEM>>>(inputs, Wself, out);
}